// round 14
// baseline (speedup 1.0000x reference)
#include <cuda_runtime.h>
#include <cuda_fp16.h>
#include <cstdint>
#include <math.h>

#define MAX_N 50000
#define MAX_E 800000
#define CH    96
#define BN_EPS 1e-5f

// -------- scratch (device globals; no allocation allowed) --------
__device__ __half d_t [MAX_N * CH];      // GEMM output (fp16, gather input)
__device__ float  d_agg[MAX_N * CH];     // aggregation output (fp32)
__device__ float  d_stats[4 * CH];
__device__ int    d_deg   [MAX_N];
__device__ int    d_starts[MAX_N + 1];
__device__ int    d_cursor[MAX_N];
__device__ int2   d_epack [MAX_E];

// ============================================================================
// Tensor-core GEMM body (mma.sync m16n8k16, f16 in / f32 accum / f16 out).
// Block: 256 threads = 8 warps as 4(M) x 2(N); tile 64 x COUT.
// ============================================================================
template<int CIN, int COUT>
__device__ __forceinline__ void gemm_mma_body(int bx,
                                              const float* __restrict__ A,
                                              const float* __restrict__ W,
                                              const float* __restrict__ stats,
                                              const float* __restrict__ gamma,
                                              const float* __restrict__ beta,
                                              __half* __restrict__ C, int nrows) {
    constexpr int TM = 64;
    constexpr int SA = CIN + 8;
    constexpr int SW = COUT + 8;
    constexpr int WN = COUT / 2;
    constexpr int NT = WN / 8;

    __shared__ __half As[TM * SA];
    __shared__ __half Ws[CIN * SW];
    __shared__ float  Sc[CIN];
    __shared__ float  Sh[CIN];

    int tid = threadIdx.x;
    int row0 = bx * TM;
    bool has_bn = (gamma != nullptr);

    if (has_bn) {
        float n = (float)nrows;
        for (int i = tid; i < CIN; i += 256) {
            float mean = stats[i] / n;
            float var  = stats[CIN + i] / n - mean * mean;
            float inv  = rsqrtf(var + BN_EPS);
            float sc   = gamma[i] * inv;
            Sc[i] = sc;
            Sh[i] = beta[i] - mean * sc;
        }
        __syncthreads();
    }

    for (int i = tid; i < CIN * COUT / 4; i += 256) {
        int k  = i / (COUT / 4);
        int c4 = (i % (COUT / 4)) * 4;
        float4 wv = *(const float4*)(W + (long)k * COUT + c4);
        *(__half2*)(Ws + k * SW + c4)     = __floats2half2_rn(wv.x, wv.y);
        *(__half2*)(Ws + k * SW + c4 + 2) = __floats2half2_rn(wv.z, wv.w);
    }
    for (int i = tid; i < TM * CIN / 4; i += 256) {
        int r  = i / (CIN / 4);
        int k4 = (i % (CIN / 4)) * 4;
        int grow = row0 + r;
        float4 v = make_float4(0.f, 0.f, 0.f, 0.f);
        if (grow < nrows)
            v = *(const float4*)(A + (long)grow * CIN + k4);
        if (has_bn) {
            v.x = fmaxf(fmaf(v.x, Sc[k4+0], Sh[k4+0]), 0.f);
            v.y = fmaxf(fmaf(v.y, Sc[k4+1], Sh[k4+1]), 0.f);
            v.z = fmaxf(fmaf(v.z, Sc[k4+2], Sh[k4+2]), 0.f);
            v.w = fmaxf(fmaf(v.w, Sc[k4+3], Sh[k4+3]), 0.f);
        }
        *(__half2*)(As + r * SA + k4)     = __floats2half2_rn(v.x, v.y);
        *(__half2*)(As + r * SA + k4 + 2) = __floats2half2_rn(v.z, v.w);
    }
    __syncthreads();

    int wid  = tid >> 5;
    int lane = tid & 31;
    int mrow = (wid & 3) * 16;
    int ncb  = (wid >> 2) * WN;

    float d[NT][4];
#pragma unroll
    for (int nt = 0; nt < NT; nt++) {
        d[nt][0] = 0.f; d[nt][1] = 0.f; d[nt][2] = 0.f; d[nt][3] = 0.f;
    }

    uint32_t as_base = (uint32_t)__cvta_generic_to_shared(As);
    uint32_t ws_base = (uint32_t)__cvta_generic_to_shared(Ws);
    int l15 = lane & 15;

#pragma unroll
    for (int k0 = 0; k0 < CIN; k0 += 16) {
        uint32_t a0, a1, a2, a3;
        uint32_t a_addr = as_base +
            (uint32_t)(((mrow + l15) * SA + k0 + ((lane >> 4) << 3)) * 2);
        asm volatile(
            "ldmatrix.sync.aligned.m8n8.x4.shared.b16 {%0,%1,%2,%3}, [%4];"
            : "=r"(a0), "=r"(a1), "=r"(a2), "=r"(a3) : "r"(a_addr));

#pragma unroll
        for (int nt = 0; nt < NT; nt++) {
            uint32_t b0, b1;
            uint32_t b_addr = ws_base +
                (uint32_t)(((k0 + l15) * SW + ncb + nt * 8) * 2);
            asm volatile(
                "ldmatrix.sync.aligned.m8n8.x2.trans.shared.b16 {%0,%1}, [%2];"
                : "=r"(b0), "=r"(b1) : "r"(b_addr));
            asm volatile(
                "mma.sync.aligned.m16n8k16.row.col.f32.f16.f16.f32 "
                "{%0,%1,%2,%3}, {%4,%5,%6,%7}, {%8,%9}, {%0,%1,%2,%3};"
                : "+f"(d[nt][0]), "+f"(d[nt][1]), "+f"(d[nt][2]), "+f"(d[nt][3])
                : "r"(a0), "r"(a1), "r"(a2), "r"(a3), "r"(b0), "r"(b1));
        }
    }

    int erow = row0 + mrow + (lane >> 2);
#pragma unroll
    for (int nt = 0; nt < NT; nt++) {
        int col = ncb + nt * 8 + (lane & 3) * 2;
        if (erow < nrows)
            *(__half2*)(C + (long)erow * COUT + col) = __floats2half2_rn(d[nt][0], d[nt][1]);
        if (erow + 8 < nrows)
            *(__half2*)(C + (long)(erow + 8) * COUT + col) = __floats2half2_rn(d[nt][2], d[nt][3]);
    }
}

template<int CIN, int COUT>
__global__ void __launch_bounds__(256)
gemm_bn_kernel(const float* __restrict__ A,
               const float* __restrict__ W,
               const float* __restrict__ stats,
               const float* __restrict__ gamma,
               const float* __restrict__ beta,
               __half* __restrict__ C, int nrows) {
    gemm_mma_body<CIN, COUT>(blockIdx.x, A, W, stats, gamma, beta, C, nrows);
}

// ---- fused: GEMM1 (blocks [0,gb)) + edge histogram (blocks [gb, gridDim)) ---
__global__ void __launch_bounds__(256)
gemm1_hist_kernel(const float* __restrict__ A,
                  const float* __restrict__ W,
                  __half* __restrict__ C, int nrows, int gb,
                  const int* __restrict__ row, int* __restrict__ deg, int E) {
    if (blockIdx.x < gb) {
        gemm_mma_body<128, 96>(blockIdx.x, A, W, nullptr, nullptr, nullptr, C, nrows);
    } else {
        int nb = gridDim.x - gb;
        int i = (blockIdx.x - gb) * 256 + threadIdx.x;
        int stride = nb * 256;
        for (; i < E; i += stride) atomicAdd(&deg[row[i]], 1);
    }
}

// ============================================================================
// CSR build: scan (also zeros stats) -> permute
// ============================================================================
__global__ void scan_kernel(const int* __restrict__ deg,
                            int* __restrict__ starts,
                            int* __restrict__ cursor,
                            float* __restrict__ stats, int N) {
    __shared__ int part[1024];
    int t = threadIdx.x;
    if (t < 4 * CH) stats[t] = 0.f;
    int chunk = (N + 1023) / 1024;
    int lo = t * chunk;
    int hi = lo + chunk; if (hi > N) hi = N; if (lo > N) lo = N;
    int s = 0;
    for (int i = lo; i < hi; i++) s += deg[i];
    part[t] = s;
    __syncthreads();
    for (int o = 1; o < 1024; o <<= 1) {
        int v = (t >= o) ? part[t - o] : 0;
        __syncthreads();
        part[t] += v;
        __syncthreads();
    }
    int base = (t == 0) ? 0 : part[t - 1];
    for (int i = lo; i < hi; i++) {
        starts[i] = base;
        cursor[i] = base;
        base += deg[i];
    }
    if (t == 1023) starts[N] = part[1023];
}

__global__ void permute_kernel(const int* __restrict__ row,
                               const int* __restrict__ col,
                               const float* __restrict__ ew,
                               int* __restrict__ cursor,
                               int2* __restrict__ epack, int E) {
    int i = blockIdx.x * blockDim.x + threadIdx.x;
    if (i >= E) return;
    int p = atomicAdd(&cursor[row[i]], 1);
    epack[p] = make_int2(col[i], __float_as_int(ew[i]));
}

// ============================================================================
// CSR gather (96 ch, fp16 src): TWO warps per node, edges split by parity.
// Each warp: lanes 0-23 own uint2 (4ch) groups, unroll-4 over its edges
// (stride 2). Even warp writes partials to smem; odd warp combines + stores.
// Block = 8 warps = 4 nodes.
// ============================================================================
__device__ __forceinline__ void h4fma(float4& acc, uint2 r, float w) {
    float2 f01 = __half22float2(*(__half2*)&r.x);
    float2 f23 = __half22float2(*(__half2*)&r.y);
    acc.x = fmaf(w, f01.x, acc.x);
    acc.y = fmaf(w, f01.y, acc.y);
    acc.z = fmaf(w, f23.x, acc.z);
    acc.w = fmaf(w, f23.y, acc.w);
}

__global__ void __launch_bounds__(256)
gather96_kernel(const int* __restrict__ starts,
                const int2* __restrict__ epack,
                const __half* __restrict__ src,
                float* __restrict__ dst, int N) {
    __shared__ float part[4][96];
    int tid  = threadIdx.x;
    int warp = tid >> 5;
    int lane = tid & 31;
    int slot = warp >> 1;      // node slot 0..3
    int wpar = warp & 1;       // edge parity
    int node = blockIdx.x * 4 + slot;
    int s = 0, e = 0;
    if (node < N) { s = __ldg(starts + node); e = __ldg(starts + node + 1); }
    bool act = lane < 24;
    float4 acc0 = make_float4(0.f,0.f,0.f,0.f);
    float4 acc1 = make_float4(0.f,0.f,0.f,0.f);
    int i = s + wpar;
    // 4 edges of this parity per iteration (8 global-edge span)
    for (; i + 6 < e; i += 8) {
        int2 p0 = __ldg(epack + i);
        int2 p1 = __ldg(epack + i + 2);
        int2 p2 = __ldg(epack + i + 4);
        int2 p3 = __ldg(epack + i + 6);
        uint2 v0 = make_uint2(0,0), v1 = v0, v2 = v0, v3 = v0;
        if (act) {
            v0 = __ldg(((const uint2*)(src + (long)p0.x * 96)) + lane);
            v1 = __ldg(((const uint2*)(src + (long)p1.x * 96)) + lane);
            v2 = __ldg(((const uint2*)(src + (long)p2.x * 96)) + lane);
            v3 = __ldg(((const uint2*)(src + (long)p3.x * 96)) + lane);
        }
        h4fma(acc0, v0, __int_as_float(p0.y));
        h4fma(acc1, v1, __int_as_float(p1.y));
        h4fma(acc0, v2, __int_as_float(p2.y));
        h4fma(acc1, v3, __int_as_float(p3.y));
    }
    for (; i < e; i += 2) {
        int2 p = __ldg(epack + i);
        uint2 v = make_uint2(0,0);
        if (act) v = __ldg(((const uint2*)(src + (long)p.x * 96)) + lane);
        h4fma(acc0, v, __int_as_float(p.y));
    }
    acc0.x += acc1.x; acc0.y += acc1.y; acc0.z += acc1.z; acc0.w += acc1.w;

    if (wpar == 0 && act)
        *(float4*)&part[slot][lane * 4] = acc0;
    __syncthreads();
    if (wpar == 1 && node < N && act) {
        float4 p = *(const float4*)&part[slot][lane * 4];
        acc0.x += p.x; acc0.y += p.y; acc0.z += p.z; acc0.w += p.w;
        ((float4*)(dst + (long)node * 96))[lane] = acc0;
    }
}

// ============================================================================
// CSR gather (64 ch, fp16 src): TWO warps per node; within each warp,
// half-warps take alternating edges (overall stride 4). Odd warp combines
// partials and runs fused +bias + log_softmax. Block = 8 warps = 4 nodes.
// ============================================================================
__global__ void __launch_bounds__(256)
gather64_lsm_kernel(const int* __restrict__ starts,
                    const int2* __restrict__ epack,
                    const __half* __restrict__ src,
                    const float* __restrict__ b,
                    float* __restrict__ out, int N) {
    __shared__ float part[4][64];
    int tid  = threadIdx.x;
    int warp = tid >> 5;
    int lane = tid & 31;
    int slot = warp >> 1;
    int wpar = warp & 1;
    int node = blockIdx.x * 4 + slot;
    int half_ = lane >> 4;
    int q = lane & 15;
    int s = 0, e = 0;
    if (node < N) { s = __ldg(starts + node); e = __ldg(starts + node + 1); }
    float4 acc0 = make_float4(0.f,0.f,0.f,0.f);
    float4 acc1 = make_float4(0.f,0.f,0.f,0.f);
    int i = s + wpar * 2 + half_;
    for (; i + 4 < e; i += 8) {
        int2 p0 = __ldg(epack + i);
        int2 p1 = __ldg(epack + i + 4);
        uint2 v0 = __ldg(((const uint2*)(src + (long)p0.x * 64)) + q);
        uint2 v1 = __ldg(((const uint2*)(src + (long)p1.x * 64)) + q);
        h4fma(acc0, v0, __int_as_float(p0.y));
        h4fma(acc1, v1, __int_as_float(p1.y));
    }
    for (; i < e; i += 4) {
        int2 p = __ldg(epack + i);
        uint2 v = __ldg(((const uint2*)(src + (long)p.x * 64)) + q);
        h4fma(acc0, v, __int_as_float(p.y));
    }
    acc0.x += acc1.x; acc0.y += acc1.y; acc0.z += acc1.z; acc0.w += acc1.w;
    // combine the two half-warp subsets within this warp
    acc0.x += __shfl_xor_sync(0xFFFFFFFFu, acc0.x, 16);
    acc0.y += __shfl_xor_sync(0xFFFFFFFFu, acc0.y, 16);
    acc0.z += __shfl_xor_sync(0xFFFFFFFFu, acc0.z, 16);
    acc0.w += __shfl_xor_sync(0xFFFFFFFFu, acc0.w, 16);

    if (wpar == 0 && half_ == 0)
        *(float4*)&part[slot][q * 4] = acc0;
    __syncthreads();
    if (wpar == 1 && node < N) {
        float4 p = *(const float4*)&part[slot][q * 4];
        acc0.x += p.x; acc0.y += p.y; acc0.z += p.z; acc0.w += p.w;
        float4 bb = __ldg(((const float4*)b) + q);
        float v0 = acc0.x + bb.x, v1 = acc0.y + bb.y;
        float v2 = acc0.z + bb.z, v3 = acc0.w + bb.w;
        float m = fmaxf(fmaxf(v0, v1), fmaxf(v2, v3));
#pragma unroll
        for (int o = 8; o; o >>= 1) m = fmaxf(m, __shfl_xor_sync(0xFFFFFFFFu, m, o));
        float sm = __expf(v0 - m) + __expf(v1 - m) + __expf(v2 - m) + __expf(v3 - m);
#pragma unroll
        for (int o = 8; o; o >>= 1) sm += __shfl_xor_sync(0xFFFFFFFFu, sm, o);
        float l = m + __logf(sm);
        if (half_ == 0)
            ((float4*)(out + (long)node * 64))[q] = make_float4(v0 - l, v1 - l, v2 - l, v3 - l);
    }
}

// -------- BN stats: register-accumulating, one thread per channel ----------
__global__ void stats96_kernel(const float* __restrict__ h,
                               float* __restrict__ stats, int nrows) {
    int c = threadIdx.x;
    float s = 0.f, q = 0.f;
    for (int r = blockIdx.x; r < nrows; r += gridDim.x) {
        float v = h[(long)r * 96 + c];
        s += v;
        q = fmaf(v, v, q);
    }
    atomicAdd(&stats[c], s);
    atomicAdd(&stats[96 + c], q);
}

// ============================================================================
extern "C" void kernel_launch(void* const* d_in, const int* in_sizes, int n_in,
                              void* d_out, int out_size) {
    const float* x   = (const float*)d_in[0];
    const float* ew  = (const float*)d_in[1];
    const int*   row = (const int*)  d_in[2];
    const int*   col = (const int*)  d_in[3];
    const float* W1  = (const float*)d_in[4];
    // b1 = d_in[5]  -- absorbed exactly by BatchNorm mean, skipped
    const float* W2  = (const float*)d_in[6];
    // b2 = d_in[7]  -- absorbed exactly by BatchNorm mean, skipped
    const float* W3  = (const float*)d_in[8];
    const float* b3  = (const float*)d_in[9];
    const float* g1  = (const float*)d_in[10];
    const float* be1 = (const float*)d_in[11];
    const float* g2  = (const float*)d_in[12];
    const float* be2 = (const float*)d_in[13];

    int N = in_sizes[0] / 128;
    int E = in_sizes[1];
    if (N > MAX_N) N = MAX_N;
    if (E > MAX_E) E = MAX_E;
    float* out = (float*)d_out;

    __half* t;
    float *agg, *stats;
    int *deg, *starts, *cursor;
    int2 *epack;
    cudaGetSymbolAddress((void**)&t,      d_t);
    cudaGetSymbolAddress((void**)&agg,    d_agg);
    cudaGetSymbolAddress((void**)&stats,  d_stats);
    cudaGetSymbolAddress((void**)&deg,    d_deg);
    cudaGetSymbolAddress((void**)&starts, d_starts);
    cudaGetSymbolAddress((void**)&cursor, d_cursor);
    cudaGetSymbolAddress((void**)&epack,  d_epack);

    float* stats1 = stats;
    float* stats2 = stats + 2 * CH;

    int gblocks = (N + 63) / 64;
    int eblocks = (E + 255) / 256;
    int pblocks = (N + 3) / 4;     // paired-warp gather blocks (4 nodes each)
    int hblocks = 512;

    // ---------------- fused GEMM1 + histogram, then scan + permute ----------
    cudaMemsetAsync(deg, 0, (long)N * sizeof(int));
    gemm1_hist_kernel<<<gblocks + hblocks, 256>>>(x, W1, t, N, gblocks,
                                                  row, deg, E);
    scan_kernel<<<1, 1024>>>(deg, starts, cursor, stats, N);
    permute_kernel<<<eblocks, 256>>>(row, col, ew, cursor, epack, E);

    // ---------------- Layer 1 (aggregate + stats) ----------------
    gather96_kernel<<<pblocks, 256>>>(starts, epack, t, agg, N);
    stats96_kernel<<<1024, 96>>>(agg, stats1, N);

    // ---------------- Layer 2 ----------------
    gemm_bn_kernel<96,96><<<gblocks, 256>>>(agg, W2, stats1, g1, be1, t, N);
    gather96_kernel<<<pblocks, 256>>>(starts, epack, t, agg, N);
    stats96_kernel<<<1024, 96>>>(agg, stats2, N);

    // ---------------- Layer 3 ----------------
    gemm_bn_kernel<96,64><<<gblocks, 256>>>(agg, W3, stats2, g2, be2, t, N);
    gather64_lsm_kernel<<<pblocks, 256>>>(starts, epack, t, b3, out, N);
}

// round 15
// speedup vs baseline: 1.1093x; 1.1093x over previous
#include <cuda_runtime.h>
#include <cuda_fp16.h>
#include <cstdint>
#include <math.h>

#define MAX_N 50000
#define MAX_E 800000
#define CH    96
#define BN_EPS 1e-5f

// -------- scratch (device globals; no allocation allowed) --------
__device__ __half d_t [MAX_N * CH];      // GEMM output (fp16, gather input)
__device__ float  d_agg[MAX_N * CH];     // aggregation output (fp32)
__device__ float  d_stats[4 * CH];
__device__ int    d_deg   [MAX_N];
__device__ int    d_starts[MAX_N + 1];
__device__ int    d_cursor[MAX_N];
__device__ int2   d_epack [MAX_E];

// ============================================================================
// Tensor-core GEMM body (mma.sync m16n8k16, f16 in / f32 accum / f16 out).
// Block: 256 threads = 8 warps as 4(M) x 2(N); tile 64 x COUT.
// ============================================================================
template<int CIN, int COUT>
__device__ __forceinline__ void gemm_mma_body(int bx,
                                              const float* __restrict__ A,
                                              const float* __restrict__ W,
                                              const float* __restrict__ stats,
                                              const float* __restrict__ gamma,
                                              const float* __restrict__ beta,
                                              __half* __restrict__ C, int nrows) {
    constexpr int TM = 64;
    constexpr int SA = CIN + 8;
    constexpr int SW = COUT + 8;
    constexpr int WN = COUT / 2;
    constexpr int NT = WN / 8;

    __shared__ __half As[TM * SA];
    __shared__ __half Ws[CIN * SW];
    __shared__ float  Sc[CIN];
    __shared__ float  Sh[CIN];

    int tid = threadIdx.x;
    int row0 = bx * TM;
    bool has_bn = (gamma != nullptr);

    if (has_bn) {
        float n = (float)nrows;
        for (int i = tid; i < CIN; i += 256) {
            float mean = stats[i] / n;
            float var  = stats[CIN + i] / n - mean * mean;
            float inv  = rsqrtf(var + BN_EPS);
            float sc   = gamma[i] * inv;
            Sc[i] = sc;
            Sh[i] = beta[i] - mean * sc;
        }
        __syncthreads();
    }

    for (int i = tid; i < CIN * COUT / 4; i += 256) {
        int k  = i / (COUT / 4);
        int c4 = (i % (COUT / 4)) * 4;
        float4 wv = *(const float4*)(W + (long)k * COUT + c4);
        *(__half2*)(Ws + k * SW + c4)     = __floats2half2_rn(wv.x, wv.y);
        *(__half2*)(Ws + k * SW + c4 + 2) = __floats2half2_rn(wv.z, wv.w);
    }
    for (int i = tid; i < TM * CIN / 4; i += 256) {
        int r  = i / (CIN / 4);
        int k4 = (i % (CIN / 4)) * 4;
        int grow = row0 + r;
        float4 v = make_float4(0.f, 0.f, 0.f, 0.f);
        if (grow < nrows)
            v = *(const float4*)(A + (long)grow * CIN + k4);
        if (has_bn) {
            v.x = fmaxf(fmaf(v.x, Sc[k4+0], Sh[k4+0]), 0.f);
            v.y = fmaxf(fmaf(v.y, Sc[k4+1], Sh[k4+1]), 0.f);
            v.z = fmaxf(fmaf(v.z, Sc[k4+2], Sh[k4+2]), 0.f);
            v.w = fmaxf(fmaf(v.w, Sc[k4+3], Sh[k4+3]), 0.f);
        }
        *(__half2*)(As + r * SA + k4)     = __floats2half2_rn(v.x, v.y);
        *(__half2*)(As + r * SA + k4 + 2) = __floats2half2_rn(v.z, v.w);
    }
    __syncthreads();

    int wid  = tid >> 5;
    int lane = tid & 31;
    int mrow = (wid & 3) * 16;
    int ncb  = (wid >> 2) * WN;

    float d[NT][4];
#pragma unroll
    for (int nt = 0; nt < NT; nt++) {
        d[nt][0] = 0.f; d[nt][1] = 0.f; d[nt][2] = 0.f; d[nt][3] = 0.f;
    }

    uint32_t as_base = (uint32_t)__cvta_generic_to_shared(As);
    uint32_t ws_base = (uint32_t)__cvta_generic_to_shared(Ws);
    int l15 = lane & 15;

#pragma unroll
    for (int k0 = 0; k0 < CIN; k0 += 16) {
        uint32_t a0, a1, a2, a3;
        uint32_t a_addr = as_base +
            (uint32_t)(((mrow + l15) * SA + k0 + ((lane >> 4) << 3)) * 2);
        asm volatile(
            "ldmatrix.sync.aligned.m8n8.x4.shared.b16 {%0,%1,%2,%3}, [%4];"
            : "=r"(a0), "=r"(a1), "=r"(a2), "=r"(a3) : "r"(a_addr));

#pragma unroll
        for (int nt = 0; nt < NT; nt++) {
            uint32_t b0, b1;
            uint32_t b_addr = ws_base +
                (uint32_t)(((k0 + l15) * SW + ncb + nt * 8) * 2);
            asm volatile(
                "ldmatrix.sync.aligned.m8n8.x2.trans.shared.b16 {%0,%1}, [%2];"
                : "=r"(b0), "=r"(b1) : "r"(b_addr));
            asm volatile(
                "mma.sync.aligned.m16n8k16.row.col.f32.f16.f16.f32 "
                "{%0,%1,%2,%3}, {%4,%5,%6,%7}, {%8,%9}, {%0,%1,%2,%3};"
                : "+f"(d[nt][0]), "+f"(d[nt][1]), "+f"(d[nt][2]), "+f"(d[nt][3])
                : "r"(a0), "r"(a1), "r"(a2), "r"(a3), "r"(b0), "r"(b1));
        }
    }

    int erow = row0 + mrow + (lane >> 2);
#pragma unroll
    for (int nt = 0; nt < NT; nt++) {
        int col = ncb + nt * 8 + (lane & 3) * 2;
        if (erow < nrows)
            *(__half2*)(C + (long)erow * COUT + col) = __floats2half2_rn(d[nt][0], d[nt][1]);
        if (erow + 8 < nrows)
            *(__half2*)(C + (long)(erow + 8) * COUT + col) = __floats2half2_rn(d[nt][2], d[nt][3]);
    }
}

template<int CIN, int COUT>
__global__ void __launch_bounds__(256)
gemm_bn_kernel(const float* __restrict__ A,
               const float* __restrict__ W,
               const float* __restrict__ stats,
               const float* __restrict__ gamma,
               const float* __restrict__ beta,
               __half* __restrict__ C, int nrows) {
    gemm_mma_body<CIN, COUT>(blockIdx.x, A, W, stats, gamma, beta, C, nrows);
}

// ---- fused: GEMM1 (blocks [0,gb)) + edge histogram (blocks [gb, gridDim)) ---
__global__ void __launch_bounds__(256)
gemm1_hist_kernel(const float* __restrict__ A,
                  const float* __restrict__ W,
                  __half* __restrict__ C, int nrows, int gb,
                  const int* __restrict__ row, int* __restrict__ deg, int E) {
    if (blockIdx.x < gb) {
        gemm_mma_body<128, 96>(blockIdx.x, A, W, nullptr, nullptr, nullptr, C, nrows);
    } else {
        int nb = gridDim.x - gb;
        int i = (blockIdx.x - gb) * 256 + threadIdx.x;
        int stride = nb * 256;
        for (; i < E; i += stride) atomicAdd(&deg[row[i]], 1);
    }
}

// ============================================================================
// CSR build: scan (also zeros stats) -> permute
// ============================================================================
__global__ void scan_kernel(const int* __restrict__ deg,
                            int* __restrict__ starts,
                            int* __restrict__ cursor,
                            float* __restrict__ stats, int N) {
    __shared__ int part[1024];
    int t = threadIdx.x;
    if (t < 4 * CH) stats[t] = 0.f;
    int chunk = (N + 1023) / 1024;
    int lo = t * chunk;
    int hi = lo + chunk; if (hi > N) hi = N; if (lo > N) lo = N;
    int s = 0;
    for (int i = lo; i < hi; i++) s += deg[i];
    part[t] = s;
    __syncthreads();
    for (int o = 1; o < 1024; o <<= 1) {
        int v = (t >= o) ? part[t - o] : 0;
        __syncthreads();
        part[t] += v;
        __syncthreads();
    }
    int base = (t == 0) ? 0 : part[t - 1];
    for (int i = lo; i < hi; i++) {
        starts[i] = base;
        cursor[i] = base;
        base += deg[i];
    }
    if (t == 1023) starts[N] = part[1023];
}

__global__ void permute_kernel(const int* __restrict__ row,
                               const int* __restrict__ col,
                               const float* __restrict__ ew,
                               int* __restrict__ cursor,
                               int2* __restrict__ epack, int E) {
    int i = blockIdx.x * blockDim.x + threadIdx.x;
    if (i >= E) return;
    int p = atomicAdd(&cursor[row[i]], 1);
    epack[p] = make_int2(col[i], __float_as_int(ew[i]));
}

// ============================================================================
// CSR gather (96 ch, fp16 src): one warp per node, lanes 0-23 own uint2
// groups. Packs-only software pipeline: next iteration's 4 packs load while
// this iteration's 4 row loads are in flight -> ~1 L2 round per iteration.
// ============================================================================
__device__ __forceinline__ void h4fma(float4& acc, uint2 r, float w) {
    float2 f01 = __half22float2(*(__half2*)&r.x);
    float2 f23 = __half22float2(*(__half2*)&r.y);
    acc.x = fmaf(w, f01.x, acc.x);
    acc.y = fmaf(w, f01.y, acc.y);
    acc.z = fmaf(w, f23.x, acc.z);
    acc.w = fmaf(w, f23.y, acc.w);
}

__global__ void gather96_kernel(const int* __restrict__ starts,
                                const int2* __restrict__ epack,
                                const __half* __restrict__ src,
                                float* __restrict__ dst, int N) {
    int w = (blockIdx.x * blockDim.x + threadIdx.x) >> 5;
    int lane = threadIdx.x & 31;
    if (w >= N) return;
    int s = __ldg(starts + w), e = __ldg(starts + w + 1);
    bool act = lane < 24;
    float4 acc0 = make_float4(0.f,0.f,0.f,0.f);
    float4 acc1 = make_float4(0.f,0.f,0.f,0.f);
    int i = s;
    if (i + 3 < e) {
        int el = e - 1;
        int2 q0 = __ldg(epack + i);
        int2 q1 = __ldg(epack + i + 1);
        int2 q2 = __ldg(epack + i + 2);
        int2 q3 = __ldg(epack + i + 3);
        for (; i + 3 < e; i += 4) {
            // issue row loads from current packs
            uint2 v0 = make_uint2(0,0), v1 = v0, v2 = v0, v3 = v0;
            if (act) {
                v0 = __ldg(((const uint2*)(src + (long)q0.x * 96)) + lane);
                v1 = __ldg(((const uint2*)(src + (long)q1.x * 96)) + lane);
                v2 = __ldg(((const uint2*)(src + (long)q2.x * 96)) + lane);
                v3 = __ldg(((const uint2*)(src + (long)q3.x * 96)) + lane);
            }
            // prefetch next packs (clamped; overlaps with row loads)
            int2 n0 = __ldg(epack + min(i + 4, el));
            int2 n1 = __ldg(epack + min(i + 5, el));
            int2 n2 = __ldg(epack + min(i + 6, el));
            int2 n3 = __ldg(epack + min(i + 7, el));
            h4fma(acc0, v0, __int_as_float(q0.y));
            h4fma(acc1, v1, __int_as_float(q1.y));
            h4fma(acc0, v2, __int_as_float(q2.y));
            h4fma(acc1, v3, __int_as_float(q3.y));
            q0 = n0; q1 = n1; q2 = n2; q3 = n3;
        }
    }
    for (; i < e; i++) {
        int2 p = __ldg(epack + i);
        uint2 v = make_uint2(0,0);
        if (act) v = __ldg(((const uint2*)(src + (long)p.x * 96)) + lane);
        h4fma(acc0, v, __int_as_float(p.y));
    }
    acc0.x += acc1.x; acc0.y += acc1.y; acc0.z += acc1.z; acc0.w += acc1.w;
    if (act) ((float4*)(dst + (long)w * 96))[lane] = acc0;
}

// ============================================================================
// CSR gather (64 ch, fp16 src): half-warps own alternating edges; packs-only
// pipeline (2 packs/half in flight ahead). Fused +bias + log_softmax.
// ============================================================================
__global__ void gather64_lsm_kernel(const int* __restrict__ starts,
                                    const int2* __restrict__ epack,
                                    const __half* __restrict__ src,
                                    const float* __restrict__ b,
                                    float* __restrict__ out, int N) {
    int w = (blockIdx.x * blockDim.x + threadIdx.x) >> 5;
    int lane = threadIdx.x & 31;
    if (w >= N) return;
    int half_ = lane >> 4;
    int q = lane & 15;
    int s = __ldg(starts + w), e = __ldg(starts + w + 1);
    float4 acc0 = make_float4(0.f,0.f,0.f,0.f);
    float4 acc1 = make_float4(0.f,0.f,0.f,0.f);
    int i = s + half_;
    if (i + 2 < e) {
        int el = e - 1;
        int2 q0 = __ldg(epack + i);
        int2 q1 = __ldg(epack + i + 2);
        for (; i + 2 < e; i += 4) {
            uint2 v0 = __ldg(((const uint2*)(src + (long)q0.x * 64)) + q);
            uint2 v1 = __ldg(((const uint2*)(src + (long)q1.x * 64)) + q);
            int2 n0 = __ldg(epack + min(i + 4, el));
            int2 n1 = __ldg(epack + min(i + 6, el));
            h4fma(acc0, v0, __int_as_float(q0.y));
            h4fma(acc1, v1, __int_as_float(q1.y));
            q0 = n0; q1 = n1;
        }
    }
    for (; i < e; i += 2) {
        int2 p = __ldg(epack + i);
        uint2 v = __ldg(((const uint2*)(src + (long)p.x * 64)) + q);
        h4fma(acc0, v, __int_as_float(p.y));
    }
    acc0.x += acc1.x; acc0.y += acc1.y; acc0.z += acc1.z; acc0.w += acc1.w;
    acc0.x += __shfl_xor_sync(0xFFFFFFFFu, acc0.x, 16);
    acc0.y += __shfl_xor_sync(0xFFFFFFFFu, acc0.y, 16);
    acc0.z += __shfl_xor_sync(0xFFFFFFFFu, acc0.z, 16);
    acc0.w += __shfl_xor_sync(0xFFFFFFFFu, acc0.w, 16);
    float4 bb = __ldg(((const float4*)b) + q);
    float v0 = acc0.x + bb.x, v1 = acc0.y + bb.y, v2 = acc0.z + bb.z, v3 = acc0.w + bb.w;
    float m = fmaxf(fmaxf(v0, v1), fmaxf(v2, v3));
#pragma unroll
    for (int o = 8; o; o >>= 1) m = fmaxf(m, __shfl_xor_sync(0xFFFFFFFFu, m, o));
    float sm = __expf(v0 - m) + __expf(v1 - m) + __expf(v2 - m) + __expf(v3 - m);
#pragma unroll
    for (int o = 8; o; o >>= 1) sm += __shfl_xor_sync(0xFFFFFFFFu, sm, o);
    float l = m + __logf(sm);
    if (half_ == 0)
        ((float4*)(out + (long)w * 64))[q] = make_float4(v0 - l, v1 - l, v2 - l, v3 - l);
}

// -------- BN stats: register-accumulating, one thread per channel ----------
__global__ void stats96_kernel(const float* __restrict__ h,
                               float* __restrict__ stats, int nrows) {
    int c = threadIdx.x;
    float s = 0.f, q = 0.f;
    for (int r = blockIdx.x; r < nrows; r += gridDim.x) {
        float v = h[(long)r * 96 + c];
        s += v;
        q = fmaf(v, v, q);
    }
    atomicAdd(&stats[c], s);
    atomicAdd(&stats[96 + c], q);
}

// ============================================================================
extern "C" void kernel_launch(void* const* d_in, const int* in_sizes, int n_in,
                              void* d_out, int out_size) {
    const float* x   = (const float*)d_in[0];
    const float* ew  = (const float*)d_in[1];
    const int*   row = (const int*)  d_in[2];
    const int*   col = (const int*)  d_in[3];
    const float* W1  = (const float*)d_in[4];
    // b1 = d_in[5]  -- absorbed exactly by BatchNorm mean, skipped
    const float* W2  = (const float*)d_in[6];
    // b2 = d_in[7]  -- absorbed exactly by BatchNorm mean, skipped
    const float* W3  = (const float*)d_in[8];
    const float* b3  = (const float*)d_in[9];
    const float* g1  = (const float*)d_in[10];
    const float* be1 = (const float*)d_in[11];
    const float* g2  = (const float*)d_in[12];
    const float* be2 = (const float*)d_in[13];

    int N = in_sizes[0] / 128;
    int E = in_sizes[1];
    if (N > MAX_N) N = MAX_N;
    if (E > MAX_E) E = MAX_E;
    float* out = (float*)d_out;

    __half* t;
    float *agg, *stats;
    int *deg, *starts, *cursor;
    int2 *epack;
    cudaGetSymbolAddress((void**)&t,      d_t);
    cudaGetSymbolAddress((void**)&agg,    d_agg);
    cudaGetSymbolAddress((void**)&stats,  d_stats);
    cudaGetSymbolAddress((void**)&deg,    d_deg);
    cudaGetSymbolAddress((void**)&starts, d_starts);
    cudaGetSymbolAddress((void**)&cursor, d_cursor);
    cudaGetSymbolAddress((void**)&epack,  d_epack);

    float* stats1 = stats;
    float* stats2 = stats + 2 * CH;

    int gblocks = (N + 63) / 64;
    int eblocks = (E + 255) / 256;
    int nwarp_blocks = (N * 32 + 255) / 256;
    int hblocks = 512;

    // ---------------- fused GEMM1 + histogram, then scan + permute ----------
    cudaMemsetAsync(deg, 0, (long)N * sizeof(int));
    gemm1_hist_kernel<<<gblocks + hblocks, 256>>>(x, W1, t, N, gblocks,
                                                  row, deg, E);
    scan_kernel<<<1, 1024>>>(deg, starts, cursor, stats, N);
    permute_kernel<<<eblocks, 256>>>(row, col, ew, cursor, epack, E);

    // ---------------- Layer 1 (aggregate + stats) ----------------
    gather96_kernel<<<nwarp_blocks, 256>>>(starts, epack, t, agg, N);
    stats96_kernel<<<1024, 96>>>(agg, stats1, N);

    // ---------------- Layer 2 ----------------
    gemm_bn_kernel<96,96><<<gblocks, 256>>>(agg, W2, stats1, g1, be1, t, N);
    gather96_kernel<<<nwarp_blocks, 256>>>(starts, epack, t, agg, N);
    stats96_kernel<<<1024, 96>>>(agg, stats2, N);

    // ---------------- Layer 3 ----------------
    gemm_bn_kernel<96,64><<<gblocks, 256>>>(agg, W3, stats2, g2, be2, t, N);
    gather64_lsm_kernel<<<nwarp_blocks, 256>>>(starts, epack, t, b3, out, N);
}

// round 16
// speedup vs baseline: 1.1683x; 1.0532x over previous
#include <cuda_runtime.h>
#include <cuda_fp16.h>
#include <cstdint>
#include <math.h>

#define MAX_N 50000
#define MAX_E 800000
#define CH    96
#define BN_EPS 1e-5f

// -------- scratch (device globals; no allocation allowed) --------
__device__ __half d_t [MAX_N * CH];      // GEMM output (fp16, gather input)
__device__ float  d_agg[MAX_N * CH];     // aggregation output (fp32)
__device__ float  d_stats[4 * CH];
__device__ int    d_deg   [MAX_N];
__device__ int    d_starts[MAX_N + 1];
__device__ int    d_cursor[MAX_N];
// 16B-aligned, padded +8 so unconditional int4 prefetch past `e` is in-bounds
__device__ __align__(16) int2 d_epack[MAX_E + 8];

// ============================================================================
// Tensor-core GEMM body (mma.sync m16n8k16, f16 in / f32 accum / f16 out).
// Block: 256 threads = 8 warps as 4(M) x 2(N); tile 64 x COUT.
// ============================================================================
template<int CIN, int COUT>
__device__ __forceinline__ void gemm_mma_body(int bx,
                                              const float* __restrict__ A,
                                              const float* __restrict__ W,
                                              const float* __restrict__ stats,
                                              const float* __restrict__ gamma,
                                              const float* __restrict__ beta,
                                              __half* __restrict__ C, int nrows) {
    constexpr int TM = 64;
    constexpr int SA = CIN + 8;
    constexpr int SW = COUT + 8;
    constexpr int WN = COUT / 2;
    constexpr int NT = WN / 8;

    __shared__ __half As[TM * SA];
    __shared__ __half Ws[CIN * SW];
    __shared__ float  Sc[CIN];
    __shared__ float  Sh[CIN];

    int tid = threadIdx.x;
    int row0 = bx * TM;
    bool has_bn = (gamma != nullptr);

    if (has_bn) {
        float n = (float)nrows;
        for (int i = tid; i < CIN; i += 256) {
            float mean = stats[i] / n;
            float var  = stats[CIN + i] / n - mean * mean;
            float inv  = rsqrtf(var + BN_EPS);
            float sc   = gamma[i] * inv;
            Sc[i] = sc;
            Sh[i] = beta[i] - mean * sc;
        }
        __syncthreads();
    }

    for (int i = tid; i < CIN * COUT / 4; i += 256) {
        int k  = i / (COUT / 4);
        int c4 = (i % (COUT / 4)) * 4;
        float4 wv = *(const float4*)(W + (long)k * COUT + c4);
        *(__half2*)(Ws + k * SW + c4)     = __floats2half2_rn(wv.x, wv.y);
        *(__half2*)(Ws + k * SW + c4 + 2) = __floats2half2_rn(wv.z, wv.w);
    }
    for (int i = tid; i < TM * CIN / 4; i += 256) {
        int r  = i / (CIN / 4);
        int k4 = (i % (CIN / 4)) * 4;
        int grow = row0 + r;
        float4 v = make_float4(0.f, 0.f, 0.f, 0.f);
        if (grow < nrows)
            v = *(const float4*)(A + (long)grow * CIN + k4);
        if (has_bn) {
            v.x = fmaxf(fmaf(v.x, Sc[k4+0], Sh[k4+0]), 0.f);
            v.y = fmaxf(fmaf(v.y, Sc[k4+1], Sh[k4+1]), 0.f);
            v.z = fmaxf(fmaf(v.z, Sc[k4+2], Sh[k4+2]), 0.f);
            v.w = fmaxf(fmaf(v.w, Sc[k4+3], Sh[k4+3]), 0.f);
        }
        *(__half2*)(As + r * SA + k4)     = __floats2half2_rn(v.x, v.y);
        *(__half2*)(As + r * SA + k4 + 2) = __floats2half2_rn(v.z, v.w);
    }
    __syncthreads();

    int wid  = tid >> 5;
    int lane = tid & 31;
    int mrow = (wid & 3) * 16;
    int ncb  = (wid >> 2) * WN;

    float d[NT][4];
#pragma unroll
    for (int nt = 0; nt < NT; nt++) {
        d[nt][0] = 0.f; d[nt][1] = 0.f; d[nt][2] = 0.f; d[nt][3] = 0.f;
    }

    uint32_t as_base = (uint32_t)__cvta_generic_to_shared(As);
    uint32_t ws_base = (uint32_t)__cvta_generic_to_shared(Ws);
    int l15 = lane & 15;

#pragma unroll
    for (int k0 = 0; k0 < CIN; k0 += 16) {
        uint32_t a0, a1, a2, a3;
        uint32_t a_addr = as_base +
            (uint32_t)(((mrow + l15) * SA + k0 + ((lane >> 4) << 3)) * 2);
        asm volatile(
            "ldmatrix.sync.aligned.m8n8.x4.shared.b16 {%0,%1,%2,%3}, [%4];"
            : "=r"(a0), "=r"(a1), "=r"(a2), "=r"(a3) : "r"(a_addr));

#pragma unroll
        for (int nt = 0; nt < NT; nt++) {
            uint32_t b0, b1;
            uint32_t b_addr = ws_base +
                (uint32_t)(((k0 + l15) * SW + ncb + nt * 8) * 2);
            asm volatile(
                "ldmatrix.sync.aligned.m8n8.x2.trans.shared.b16 {%0,%1}, [%2];"
                : "=r"(b0), "=r"(b1) : "r"(b_addr));
            asm volatile(
                "mma.sync.aligned.m16n8k16.row.col.f32.f16.f16.f32 "
                "{%0,%1,%2,%3}, {%4,%5,%6,%7}, {%8,%9}, {%0,%1,%2,%3};"
                : "+f"(d[nt][0]), "+f"(d[nt][1]), "+f"(d[nt][2]), "+f"(d[nt][3])
                : "r"(a0), "r"(a1), "r"(a2), "r"(a3), "r"(b0), "r"(b1));
        }
    }

    int erow = row0 + mrow + (lane >> 2);
#pragma unroll
    for (int nt = 0; nt < NT; nt++) {
        int col = ncb + nt * 8 + (lane & 3) * 2;
        if (erow < nrows)
            *(__half2*)(C + (long)erow * COUT + col) = __floats2half2_rn(d[nt][0], d[nt][1]);
        if (erow + 8 < nrows)
            *(__half2*)(C + (long)(erow + 8) * COUT + col) = __floats2half2_rn(d[nt][2], d[nt][3]);
    }
}

template<int CIN, int COUT>
__global__ void __launch_bounds__(256)
gemm_bn_kernel(const float* __restrict__ A,
               const float* __restrict__ W,
               const float* __restrict__ stats,
               const float* __restrict__ gamma,
               const float* __restrict__ beta,
               __half* __restrict__ C, int nrows) {
    gemm_mma_body<CIN, COUT>(blockIdx.x, A, W, stats, gamma, beta, C, nrows);
}

// ---- fused: GEMM1 (blocks [0,gb)) + edge histogram (blocks [gb, gridDim)) ---
__global__ void __launch_bounds__(256)
gemm1_hist_kernel(const float* __restrict__ A,
                  const float* __restrict__ W,
                  __half* __restrict__ C, int nrows, int gb,
                  const int* __restrict__ row, int* __restrict__ deg, int E) {
    if (blockIdx.x < gb) {
        gemm_mma_body<128, 96>(blockIdx.x, A, W, nullptr, nullptr, nullptr, C, nrows);
    } else {
        int nb = gridDim.x - gb;
        int i = (blockIdx.x - gb) * 256 + threadIdx.x;
        int stride = nb * 256;
        for (; i < E; i += stride) atomicAdd(&deg[row[i]], 1);
    }
}

// ============================================================================
// CSR build: scan (also zeros stats) -> permute
// ============================================================================
__global__ void scan_kernel(const int* __restrict__ deg,
                            int* __restrict__ starts,
                            int* __restrict__ cursor,
                            float* __restrict__ stats, int N) {
    __shared__ int part[1024];
    int t = threadIdx.x;
    if (t < 4 * CH) stats[t] = 0.f;
    int chunk = (N + 1023) / 1024;
    int lo = t * chunk;
    int hi = lo + chunk; if (hi > N) hi = N; if (lo > N) lo = N;
    int s = 0;
    for (int i = lo; i < hi; i++) s += deg[i];
    part[t] = s;
    __syncthreads();
    for (int o = 1; o < 1024; o <<= 1) {
        int v = (t >= o) ? part[t - o] : 0;
        __syncthreads();
        part[t] += v;
        __syncthreads();
    }
    int base = (t == 0) ? 0 : part[t - 1];
    for (int i = lo; i < hi; i++) {
        starts[i] = base;
        cursor[i] = base;
        base += deg[i];
    }
    if (t == 1023) starts[N] = part[1023];
}

__global__ void permute_kernel(const int* __restrict__ row,
                               const int* __restrict__ col,
                               const float* __restrict__ ew,
                               int* __restrict__ cursor,
                               int2* __restrict__ epack, int E) {
    int i = blockIdx.x * blockDim.x + threadIdx.x;
    if (i >= E) return;
    int p = atomicAdd(&cursor[row[i]], 1);
    epack[p] = make_int2(col[i], __float_as_int(ew[i]));
}

// ============================================================================
// CSR gather (96 ch, fp16 src): one warp per node, lanes 0-23 own uint2
// groups. int4 pack-PAIR loads (2 edges per LDG) + packs-only pipeline.
// ============================================================================
__device__ __forceinline__ void h4fma(float4& acc, uint2 r, float w) {
    float2 f01 = __half22float2(*(__half2*)&r.x);
    float2 f23 = __half22float2(*(__half2*)&r.y);
    acc.x = fmaf(w, f01.x, acc.x);
    acc.y = fmaf(w, f01.y, acc.y);
    acc.z = fmaf(w, f23.x, acc.z);
    acc.w = fmaf(w, f23.y, acc.w);
}

__global__ void gather96_kernel(const int* __restrict__ starts,
                                const int2* __restrict__ epack,
                                const __half* __restrict__ src,
                                float* __restrict__ dst, int N) {
    int w = (blockIdx.x * blockDim.x + threadIdx.x) >> 5;
    int lane = threadIdx.x & 31;
    if (w >= N) return;
    int s = __ldg(starts + w), e = __ldg(starts + w + 1);
    bool act = lane < 24;
    float4 acc0 = make_float4(0.f,0.f,0.f,0.f);
    float4 acc1 = make_float4(0.f,0.f,0.f,0.f);
    int i = s;
    // align to even edge index for int4 pack pairs
    if ((i & 1) && i < e) {
        int2 p = __ldg(epack + i);
        uint2 v = make_uint2(0,0);
        if (act) v = __ldg(((const uint2*)(src + (long)p.x * 96)) + lane);
        h4fma(acc0, v, __int_as_float(p.y));
        i++;
    }
    if (i + 3 < e) {
        const int4* ep4 = (const int4*)epack;   // 16B-aligned
        int j = i >> 1;
        int4 pp0 = __ldg(ep4 + j);      // edges i,   i+1
        int4 pp1 = __ldg(ep4 + j + 1);  // edges i+2, i+3
        for (; i + 3 < e; i += 4, j += 2) {
            uint2 v0 = make_uint2(0,0), v1 = v0, v2 = v0, v3 = v0;
            if (act) {
                v0 = __ldg(((const uint2*)(src + (long)pp0.x * 96)) + lane);
                v1 = __ldg(((const uint2*)(src + (long)pp0.z * 96)) + lane);
                v2 = __ldg(((const uint2*)(src + (long)pp1.x * 96)) + lane);
                v3 = __ldg(((const uint2*)(src + (long)pp1.z * 96)) + lane);
            }
            // prefetch next pair (array padded +8 -> always in-bounds)
            int4 np0 = __ldg(ep4 + j + 2);
            int4 np1 = __ldg(ep4 + j + 3);
            h4fma(acc0, v0, __int_as_float(pp0.y));
            h4fma(acc1, v1, __int_as_float(pp0.w));
            h4fma(acc0, v2, __int_as_float(pp1.y));
            h4fma(acc1, v3, __int_as_float(pp1.w));
            pp0 = np0; pp1 = np1;
        }
    }
    for (; i < e; i++) {
        int2 p = __ldg(epack + i);
        uint2 v = make_uint2(0,0);
        if (act) v = __ldg(((const uint2*)(src + (long)p.x * 96)) + lane);
        h4fma(acc0, v, __int_as_float(p.y));
    }
    acc0.x += acc1.x; acc0.y += acc1.y; acc0.z += acc1.z; acc0.w += acc1.w;
    if (act) ((float4*)(dst + (long)w * 96))[lane] = acc0;
}

// ============================================================================
// CSR gather (64 ch, fp16 src): half-warps own alternating edges; packs-only
// pipeline. Fused +bias + log_softmax.
// ============================================================================
__global__ void gather64_lsm_kernel(const int* __restrict__ starts,
                                    const int2* __restrict__ epack,
                                    const __half* __restrict__ src,
                                    const float* __restrict__ b,
                                    float* __restrict__ out, int N) {
    int w = (blockIdx.x * blockDim.x + threadIdx.x) >> 5;
    int lane = threadIdx.x & 31;
    if (w >= N) return;
    int half_ = lane >> 4;
    int q = lane & 15;
    int s = __ldg(starts + w), e = __ldg(starts + w + 1);
    float4 acc0 = make_float4(0.f,0.f,0.f,0.f);
    float4 acc1 = make_float4(0.f,0.f,0.f,0.f);
    int i = s + half_;
    if (i + 2 < e) {
        int el = e - 1;
        int2 q0 = __ldg(epack + i);
        int2 q1 = __ldg(epack + i + 2);
        for (; i + 2 < e; i += 4) {
            uint2 v0 = __ldg(((const uint2*)(src + (long)q0.x * 64)) + q);
            uint2 v1 = __ldg(((const uint2*)(src + (long)q1.x * 64)) + q);
            int2 n0 = __ldg(epack + min(i + 4, el));
            int2 n1 = __ldg(epack + min(i + 6, el));
            h4fma(acc0, v0, __int_as_float(q0.y));
            h4fma(acc1, v1, __int_as_float(q1.y));
            q0 = n0; q1 = n1;
        }
    }
    for (; i < e; i += 2) {
        int2 p = __ldg(epack + i);
        uint2 v = __ldg(((const uint2*)(src + (long)p.x * 64)) + q);
        h4fma(acc0, v, __int_as_float(p.y));
    }
    acc0.x += acc1.x; acc0.y += acc1.y; acc0.z += acc1.z; acc0.w += acc1.w;
    acc0.x += __shfl_xor_sync(0xFFFFFFFFu, acc0.x, 16);
    acc0.y += __shfl_xor_sync(0xFFFFFFFFu, acc0.y, 16);
    acc0.z += __shfl_xor_sync(0xFFFFFFFFu, acc0.z, 16);
    acc0.w += __shfl_xor_sync(0xFFFFFFFFu, acc0.w, 16);
    float4 bb = __ldg(((const float4*)b) + q);
    float v0 = acc0.x + bb.x, v1 = acc0.y + bb.y, v2 = acc0.z + bb.z, v3 = acc0.w + bb.w;
    float m = fmaxf(fmaxf(v0, v1), fmaxf(v2, v3));
#pragma unroll
    for (int o = 8; o; o >>= 1) m = fmaxf(m, __shfl_xor_sync(0xFFFFFFFFu, m, o));
    float sm = __expf(v0 - m) + __expf(v1 - m) + __expf(v2 - m) + __expf(v3 - m);
#pragma unroll
    for (int o = 8; o; o >>= 1) sm += __shfl_xor_sync(0xFFFFFFFFu, sm, o);
    float l = m + __logf(sm);
    if (half_ == 0)
        ((float4*)(out + (long)w * 64))[q] = make_float4(v0 - l, v1 - l, v2 - l, v3 - l);
}

// ============================================================================
// BN stats: 192 threads/block. Thread (g = tid%24, j = tid/24) accumulates
// float4 partials for channel group g over rows strided by 8*gridDim.
// smem tree-reduce over j, then one atomicAdd per channel per block.
// ============================================================================
__global__ void __launch_bounds__(192)
stats96_kernel(const float* __restrict__ h,
               float* __restrict__ stats, int nrows) {
    __shared__ float red[2][8][96];
    int tid = threadIdx.x;
    int g = tid % 24;
    int j = tid / 24;
    float4 s = make_float4(0.f,0.f,0.f,0.f);
    float4 q = make_float4(0.f,0.f,0.f,0.f);
    for (int r = blockIdx.x * 8 + j; r < nrows; r += gridDim.x * 8) {
        float4 v = *(const float4*)(h + (long)r * 96 + g * 4);
        s.x += v.x; s.y += v.y; s.z += v.z; s.w += v.w;
        q.x = fmaf(v.x, v.x, q.x);
        q.y = fmaf(v.y, v.y, q.y);
        q.z = fmaf(v.z, v.z, q.z);
        q.w = fmaf(v.w, v.w, q.w);
    }
    *(float4*)&red[0][j][g * 4] = s;
    *(float4*)&red[1][j][g * 4] = q;
    __syncthreads();
    int part = tid / 96;    // 0 = sum, 1 = sumsq
    int c = tid % 96;
    float t = 0.f;
#pragma unroll
    for (int k = 0; k < 8; k++) t += red[part][k][c];
    atomicAdd(&stats[part * 96 + c], t);
}

// ============================================================================
extern "C" void kernel_launch(void* const* d_in, const int* in_sizes, int n_in,
                              void* d_out, int out_size) {
    const float* x   = (const float*)d_in[0];
    const float* ew  = (const float*)d_in[1];
    const int*   row = (const int*)  d_in[2];
    const int*   col = (const int*)  d_in[3];
    const float* W1  = (const float*)d_in[4];
    // b1 = d_in[5]  -- absorbed exactly by BatchNorm mean, skipped
    const float* W2  = (const float*)d_in[6];
    // b2 = d_in[7]  -- absorbed exactly by BatchNorm mean, skipped
    const float* W3  = (const float*)d_in[8];
    const float* b3  = (const float*)d_in[9];
    const float* g1  = (const float*)d_in[10];
    const float* be1 = (const float*)d_in[11];
    const float* g2  = (const float*)d_in[12];
    const float* be2 = (const float*)d_in[13];

    int N = in_sizes[0] / 128;
    int E = in_sizes[1];
    if (N > MAX_N) N = MAX_N;
    if (E > MAX_E) E = MAX_E;
    float* out = (float*)d_out;

    __half* t;
    float *agg, *stats;
    int *deg, *starts, *cursor;
    int2 *epack;
    cudaGetSymbolAddress((void**)&t,      d_t);
    cudaGetSymbolAddress((void**)&agg,    d_agg);
    cudaGetSymbolAddress((void**)&stats,  d_stats);
    cudaGetSymbolAddress((void**)&deg,    d_deg);
    cudaGetSymbolAddress((void**)&starts, d_starts);
    cudaGetSymbolAddress((void**)&cursor, d_cursor);
    cudaGetSymbolAddress((void**)&epack,  d_epack);

    float* stats1 = stats;
    float* stats2 = stats + 2 * CH;

    int gblocks = (N + 63) / 64;
    int eblocks = (E + 255) / 256;
    int nwarp_blocks = (N * 32 + 255) / 256;
    int hblocks = 512;

    // ---------------- fused GEMM1 + histogram, then scan + permute ----------
    cudaMemsetAsync(deg, 0, (long)N * sizeof(int));
    gemm1_hist_kernel<<<gblocks + hblocks, 256>>>(x, W1, t, N, gblocks,
                                                  row, deg, E);
    scan_kernel<<<1, 1024>>>(deg, starts, cursor, stats, N);
    permute_kernel<<<eblocks, 256>>>(row, col, ew, cursor, epack, E);

    // ---------------- Layer 1 (aggregate + stats) ----------------
    gather96_kernel<<<nwarp_blocks, 256>>>(starts, epack, t, agg, N);
    stats96_kernel<<<256, 192>>>(agg, stats1, N);

    // ---------------- Layer 2 ----------------
    gemm_bn_kernel<96,96><<<gblocks, 256>>>(agg, W2, stats1, g1, be1, t, N);
    gather96_kernel<<<nwarp_blocks, 256>>>(starts, epack, t, agg, N);
    stats96_kernel<<<256, 192>>>(agg, stats2, N);

    // ---------------- Layer 3 ----------------
    gemm_bn_kernel<96,64><<<gblocks, 256>>>(agg, W3, stats2, g2, be2, t, N);
    gather64_lsm_kernel<<<nwarp_blocks, 256>>>(starts, epack, t, b3, out, N);
}

// round 17
// speedup vs baseline: 1.1935x; 1.0216x over previous
#include <cuda_runtime.h>
#include <cuda_fp16.h>
#include <cstdint>
#include <math.h>

#define MAX_N 50000
#define MAX_E 800000
#define CH    96
#define BN_EPS 1e-5f

// -------- scratch (device globals; no allocation allowed) --------
__device__ __half d_t [MAX_N * CH];      // GEMM output (fp16, gather input)
__device__ float  d_agg[MAX_N * CH];     // aggregation output (fp32)
__device__ float  d_stats[4 * CH];
__device__ int    d_deg   [MAX_N];
__device__ int    d_starts[MAX_N + 1];
__device__ int    d_cursor[MAX_N];
__device__ __align__(16) int2 d_epack[MAX_E + 8];

// ============================================================================
// Tensor-core GEMM body (mma.sync m16n8k16, f16 in / f32 accum / f16 out).
// Block: 256 threads = 8 warps as 4(M) x 2(N); tile 64 x COUT.
// ============================================================================
template<int CIN, int COUT>
__device__ __forceinline__ void gemm_mma_body(int bx,
                                              const float* __restrict__ A,
                                              const float* __restrict__ W,
                                              const float* __restrict__ stats,
                                              const float* __restrict__ gamma,
                                              const float* __restrict__ beta,
                                              __half* __restrict__ C, int nrows) {
    constexpr int TM = 64;
    constexpr int SA = CIN + 8;
    constexpr int SW = COUT + 8;
    constexpr int WN = COUT / 2;
    constexpr int NT = WN / 8;

    __shared__ __half As[TM * SA];
    __shared__ __half Ws[CIN * SW];
    __shared__ float  Sc[CIN];
    __shared__ float  Sh[CIN];

    int tid = threadIdx.x;
    int row0 = bx * TM;
    bool has_bn = (gamma != nullptr);

    if (has_bn) {
        float n = (float)nrows;
        for (int i = tid; i < CIN; i += 256) {
            float mean = stats[i] / n;
            float var  = stats[CIN + i] / n - mean * mean;
            float inv  = rsqrtf(var + BN_EPS);
            float sc   = gamma[i] * inv;
            Sc[i] = sc;
            Sh[i] = beta[i] - mean * sc;
        }
        __syncthreads();
    }

    for (int i = tid; i < CIN * COUT / 4; i += 256) {
        int k  = i / (COUT / 4);
        int c4 = (i % (COUT / 4)) * 4;
        float4 wv = *(const float4*)(W + (long)k * COUT + c4);
        *(__half2*)(Ws + k * SW + c4)     = __floats2half2_rn(wv.x, wv.y);
        *(__half2*)(Ws + k * SW + c4 + 2) = __floats2half2_rn(wv.z, wv.w);
    }
    for (int i = tid; i < TM * CIN / 4; i += 256) {
        int r  = i / (CIN / 4);
        int k4 = (i % (CIN / 4)) * 4;
        int grow = row0 + r;
        float4 v = make_float4(0.f, 0.f, 0.f, 0.f);
        if (grow < nrows)
            v = *(const float4*)(A + (long)grow * CIN + k4);
        if (has_bn) {
            v.x = fmaxf(fmaf(v.x, Sc[k4+0], Sh[k4+0]), 0.f);
            v.y = fmaxf(fmaf(v.y, Sc[k4+1], Sh[k4+1]), 0.f);
            v.z = fmaxf(fmaf(v.z, Sc[k4+2], Sh[k4+2]), 0.f);
            v.w = fmaxf(fmaf(v.w, Sc[k4+3], Sh[k4+3]), 0.f);
        }
        *(__half2*)(As + r * SA + k4)     = __floats2half2_rn(v.x, v.y);
        *(__half2*)(As + r * SA + k4 + 2) = __floats2half2_rn(v.z, v.w);
    }
    __syncthreads();

    int wid  = tid >> 5;
    int lane = tid & 31;
    int mrow = (wid & 3) * 16;
    int ncb  = (wid >> 2) * WN;

    float d[NT][4];
#pragma unroll
    for (int nt = 0; nt < NT; nt++) {
        d[nt][0] = 0.f; d[nt][1] = 0.f; d[nt][2] = 0.f; d[nt][3] = 0.f;
    }

    uint32_t as_base = (uint32_t)__cvta_generic_to_shared(As);
    uint32_t ws_base = (uint32_t)__cvta_generic_to_shared(Ws);
    int l15 = lane & 15;

#pragma unroll
    for (int k0 = 0; k0 < CIN; k0 += 16) {
        uint32_t a0, a1, a2, a3;
        uint32_t a_addr = as_base +
            (uint32_t)(((mrow + l15) * SA + k0 + ((lane >> 4) << 3)) * 2);
        asm volatile(
            "ldmatrix.sync.aligned.m8n8.x4.shared.b16 {%0,%1,%2,%3}, [%4];"
            : "=r"(a0), "=r"(a1), "=r"(a2), "=r"(a3) : "r"(a_addr));

#pragma unroll
        for (int nt = 0; nt < NT; nt++) {
            uint32_t b0, b1;
            uint32_t b_addr = ws_base +
                (uint32_t)(((k0 + l15) * SW + ncb + nt * 8) * 2);
            asm volatile(
                "ldmatrix.sync.aligned.m8n8.x2.trans.shared.b16 {%0,%1}, [%2];"
                : "=r"(b0), "=r"(b1) : "r"(b_addr));
            asm volatile(
                "mma.sync.aligned.m16n8k16.row.col.f32.f16.f16.f32 "
                "{%0,%1,%2,%3}, {%4,%5,%6,%7}, {%8,%9}, {%0,%1,%2,%3};"
                : "+f"(d[nt][0]), "+f"(d[nt][1]), "+f"(d[nt][2]), "+f"(d[nt][3])
                : "r"(a0), "r"(a1), "r"(a2), "r"(a3), "r"(b0), "r"(b1));
        }
    }

    int erow = row0 + mrow + (lane >> 2);
#pragma unroll
    for (int nt = 0; nt < NT; nt++) {
        int col = ncb + nt * 8 + (lane & 3) * 2;
        if (erow < nrows)
            *(__half2*)(C + (long)erow * COUT + col) = __floats2half2_rn(d[nt][0], d[nt][1]);
        if (erow + 8 < nrows)
            *(__half2*)(C + (long)(erow + 8) * COUT + col) = __floats2half2_rn(d[nt][2], d[nt][3]);
    }
}

template<int CIN, int COUT>
__global__ void __launch_bounds__(256)
gemm_bn_kernel(const float* __restrict__ A,
               const float* __restrict__ W,
               const float* __restrict__ stats,
               const float* __restrict__ gamma,
               const float* __restrict__ beta,
               __half* __restrict__ C, int nrows) {
    gemm_mma_body<CIN, COUT>(blockIdx.x, A, W, stats, gamma, beta, C, nrows);
}

// ---- fused: GEMM1 (blocks [0,gb)) + edge histogram (blocks [gb, gridDim)) ---
__global__ void __launch_bounds__(256)
gemm1_hist_kernel(const float* __restrict__ A,
                  const float* __restrict__ W,
                  __half* __restrict__ C, int nrows, int gb,
                  const int* __restrict__ row, int* __restrict__ deg, int E) {
    if (blockIdx.x < gb) {
        gemm_mma_body<128, 96>(blockIdx.x, A, W, nullptr, nullptr, nullptr, C, nrows);
    } else {
        int nb = gridDim.x - gb;
        int i = (blockIdx.x - gb) * 256 + threadIdx.x;
        int stride = nb * 256;
        for (; i < E; i += stride) atomicAdd(&deg[row[i]], 1);
    }
}

// ============================================================================
// CSR build: scan (also zeros stats) -> permute
// ============================================================================
__global__ void scan_kernel(const int* __restrict__ deg,
                            int* __restrict__ starts,
                            int* __restrict__ cursor,
                            float* __restrict__ stats, int N) {
    __shared__ int part[1024];
    int t = threadIdx.x;
    if (t < 4 * CH) stats[t] = 0.f;
    int chunk = (N + 1023) / 1024;
    int lo = t * chunk;
    int hi = lo + chunk; if (hi > N) hi = N; if (lo > N) lo = N;
    int s = 0;
    for (int i = lo; i < hi; i++) s += deg[i];
    part[t] = s;
    __syncthreads();
    for (int o = 1; o < 1024; o <<= 1) {
        int v = (t >= o) ? part[t - o] : 0;
        __syncthreads();
        part[t] += v;
        __syncthreads();
    }
    int base = (t == 0) ? 0 : part[t - 1];
    for (int i = lo; i < hi; i++) {
        starts[i] = base;
        cursor[i] = base;
        base += deg[i];
    }
    if (t == 1023) starts[N] = part[1023];
}

__global__ void permute_kernel(const int* __restrict__ row,
                               const int* __restrict__ col,
                               const float* __restrict__ ew,
                               int* __restrict__ cursor,
                               int2* __restrict__ epack, int E) {
    int i = blockIdx.x * blockDim.x + threadIdx.x;
    if (i >= E) return;
    int p = atomicAdd(&cursor[row[i]], 1);
    epack[p] = make_int2(col[i], __float_as_int(ew[i]));
}

// ============================================================================
// CSR gather (96 ch, fp16 src): one warp per node, lanes 0-23 own uint2
// groups. Packs-only software pipeline (round-15 proven form).
// ============================================================================
__device__ __forceinline__ void h4fma(float4& acc, uint2 r, float w) {
    float2 f01 = __half22float2(*(__half2*)&r.x);
    float2 f23 = __half22float2(*(__half2*)&r.y);
    acc.x = fmaf(w, f01.x, acc.x);
    acc.y = fmaf(w, f01.y, acc.y);
    acc.z = fmaf(w, f23.x, acc.z);
    acc.w = fmaf(w, f23.y, acc.w);
}

__global__ void gather96_kernel(const int* __restrict__ starts,
                                const int2* __restrict__ epack,
                                const __half* __restrict__ src,
                                float* __restrict__ dst, int N) {
    int w = (blockIdx.x * blockDim.x + threadIdx.x) >> 5;
    int lane = threadIdx.x & 31;
    if (w >= N) return;
    int s = __ldg(starts + w), e = __ldg(starts + w + 1);
    bool act = lane < 24;
    float4 acc0 = make_float4(0.f,0.f,0.f,0.f);
    float4 acc1 = make_float4(0.f,0.f,0.f,0.f);
    int i = s;
    if (i + 3 < e) {
        int el = e - 1;
        int2 q0 = __ldg(epack + i);
        int2 q1 = __ldg(epack + i + 1);
        int2 q2 = __ldg(epack + i + 2);
        int2 q3 = __ldg(epack + i + 3);
        for (; i + 3 < e; i += 4) {
            uint2 v0 = make_uint2(0,0), v1 = v0, v2 = v0, v3 = v0;
            if (act) {
                v0 = __ldg(((const uint2*)(src + (long)q0.x * 96)) + lane);
                v1 = __ldg(((const uint2*)(src + (long)q1.x * 96)) + lane);
                v2 = __ldg(((const uint2*)(src + (long)q2.x * 96)) + lane);
                v3 = __ldg(((const uint2*)(src + (long)q3.x * 96)) + lane);
            }
            int2 n0 = __ldg(epack + min(i + 4, el));
            int2 n1 = __ldg(epack + min(i + 5, el));
            int2 n2 = __ldg(epack + min(i + 6, el));
            int2 n3 = __ldg(epack + min(i + 7, el));
            h4fma(acc0, v0, __int_as_float(q0.y));
            h4fma(acc1, v1, __int_as_float(q1.y));
            h4fma(acc0, v2, __int_as_float(q2.y));
            h4fma(acc1, v3, __int_as_float(q3.y));
            q0 = n0; q1 = n1; q2 = n2; q3 = n3;
        }
    }
    for (; i < e; i++) {
        int2 p = __ldg(epack + i);
        uint2 v = make_uint2(0,0);
        if (act) v = __ldg(((const uint2*)(src + (long)p.x * 96)) + lane);
        h4fma(acc0, v, __int_as_float(p.y));
    }
    acc0.x += acc1.x; acc0.y += acc1.y; acc0.z += acc1.z; acc0.w += acc1.w;
    if (act) ((float4*)(dst + (long)w * 96))[lane] = acc0;
}

// ============================================================================
// CSR gather (64 ch, fp16 src): half-warps own alternating edges; packs-only
// pipeline. Fused +bias + log_softmax.
// ============================================================================
__global__ void gather64_lsm_kernel(const int* __restrict__ starts,
                                    const int2* __restrict__ epack,
                                    const __half* __restrict__ src,
                                    const float* __restrict__ b,
                                    float* __restrict__ out, int N) {
    int w = (blockIdx.x * blockDim.x + threadIdx.x) >> 5;
    int lane = threadIdx.x & 31;
    if (w >= N) return;
    int half_ = lane >> 4;
    int q = lane & 15;
    int s = __ldg(starts + w), e = __ldg(starts + w + 1);
    float4 acc0 = make_float4(0.f,0.f,0.f,0.f);
    float4 acc1 = make_float4(0.f,0.f,0.f,0.f);
    int i = s + half_;
    if (i + 2 < e) {
        int el = e - 1;
        int2 q0 = __ldg(epack + i);
        int2 q1 = __ldg(epack + i + 2);
        for (; i + 2 < e; i += 4) {
            uint2 v0 = __ldg(((const uint2*)(src + (long)q0.x * 64)) + q);
            uint2 v1 = __ldg(((const uint2*)(src + (long)q1.x * 64)) + q);
            int2 n0 = __ldg(epack + min(i + 4, el));
            int2 n1 = __ldg(epack + min(i + 6, el));
            h4fma(acc0, v0, __int_as_float(q0.y));
            h4fma(acc1, v1, __int_as_float(q1.y));
            q0 = n0; q1 = n1;
        }
    }
    for (; i < e; i += 2) {
        int2 p = __ldg(epack + i);
        uint2 v = __ldg(((const uint2*)(src + (long)p.x * 64)) + q);
        h4fma(acc0, v, __int_as_float(p.y));
    }
    acc0.x += acc1.x; acc0.y += acc1.y; acc0.z += acc1.z; acc0.w += acc1.w;
    acc0.x += __shfl_xor_sync(0xFFFFFFFFu, acc0.x, 16);
    acc0.y += __shfl_xor_sync(0xFFFFFFFFu, acc0.y, 16);
    acc0.z += __shfl_xor_sync(0xFFFFFFFFu, acc0.z, 16);
    acc0.w += __shfl_xor_sync(0xFFFFFFFFu, acc0.w, 16);
    float4 bb = __ldg(((const float4*)b) + q);
    float v0 = acc0.x + bb.x, v1 = acc0.y + bb.y, v2 = acc0.z + bb.z, v3 = acc0.w + bb.w;
    float m = fmaxf(fmaxf(v0, v1), fmaxf(v2, v3));
#pragma unroll
    for (int o = 8; o; o >>= 1) m = fmaxf(m, __shfl_xor_sync(0xFFFFFFFFu, m, o));
    float sm = __expf(v0 - m) + __expf(v1 - m) + __expf(v2 - m) + __expf(v3 - m);
#pragma unroll
    for (int o = 8; o; o >>= 1) sm += __shfl_xor_sync(0xFFFFFFFFu, sm, o);
    float l = m + __logf(sm);
    if (half_ == 0)
        ((float4*)(out + (long)w * 64))[q] = make_float4(v0 - l, v1 - l, v2 - l, v3 - l);
}

// ============================================================================
// BN stats: 192 threads/block, float4 per-thread partials, smem tree-reduce,
// one atomicAdd per channel per block (round-16 proven form).
// ============================================================================
__global__ void __launch_bounds__(192)
stats96_kernel(const float* __restrict__ h,
               float* __restrict__ stats, int nrows) {
    __shared__ float red[2][8][96];
    int tid = threadIdx.x;
    int g = tid % 24;
    int j = tid / 24;
    float4 s = make_float4(0.f,0.f,0.f,0.f);
    float4 q = make_float4(0.f,0.f,0.f,0.f);
    for (int r = blockIdx.x * 8 + j; r < nrows; r += gridDim.x * 8) {
        float4 v = *(const float4*)(h + (long)r * 96 + g * 4);
        s.x += v.x; s.y += v.y; s.z += v.z; s.w += v.w;
        q.x = fmaf(v.x, v.x, q.x);
        q.y = fmaf(v.y, v.y, q.y);
        q.z = fmaf(v.z, v.z, q.z);
        q.w = fmaf(v.w, v.w, q.w);
    }
    *(float4*)&red[0][j][g * 4] = s;
    *(float4*)&red[1][j][g * 4] = q;
    __syncthreads();
    int part = tid / 96;    // 0 = sum, 1 = sumsq
    int c = tid % 96;
    float t = 0.f;
#pragma unroll
    for (int k = 0; k < 8; k++) t += red[part][k][c];
    atomicAdd(&stats[part * 96 + c], t);
}

// ============================================================================
extern "C" void kernel_launch(void* const* d_in, const int* in_sizes, int n_in,
                              void* d_out, int out_size) {
    const float* x   = (const float*)d_in[0];
    const float* ew  = (const float*)d_in[1];
    const int*   row = (const int*)  d_in[2];
    const int*   col = (const int*)  d_in[3];
    const float* W1  = (const float*)d_in[4];
    // b1 = d_in[5]  -- absorbed exactly by BatchNorm mean, skipped
    const float* W2  = (const float*)d_in[6];
    // b2 = d_in[7]  -- absorbed exactly by BatchNorm mean, skipped
    const float* W3  = (const float*)d_in[8];
    const float* b3  = (const float*)d_in[9];
    const float* g1  = (const float*)d_in[10];
    const float* be1 = (const float*)d_in[11];
    const float* g2  = (const float*)d_in[12];
    const float* be2 = (const float*)d_in[13];

    int N = in_sizes[0] / 128;
    int E = in_sizes[1];
    if (N > MAX_N) N = MAX_N;
    if (E > MAX_E) E = MAX_E;
    float* out = (float*)d_out;

    __half* t;
    float *agg, *stats;
    int *deg, *starts, *cursor;
    int2 *epack;
    cudaGetSymbolAddress((void**)&t,      d_t);
    cudaGetSymbolAddress((void**)&agg,    d_agg);
    cudaGetSymbolAddress((void**)&stats,  d_stats);
    cudaGetSymbolAddress((void**)&deg,    d_deg);
    cudaGetSymbolAddress((void**)&starts, d_starts);
    cudaGetSymbolAddress((void**)&cursor, d_cursor);
    cudaGetSymbolAddress((void**)&epack,  d_epack);

    float* stats1 = stats;
    float* stats2 = stats + 2 * CH;

    int gblocks = (N + 63) / 64;
    int eblocks = (E + 255) / 256;
    int nwarp_blocks = (N * 32 + 255) / 256;
    int hblocks = 512;

    // ---------------- fused GEMM1 + histogram, then scan + permute ----------
    cudaMemsetAsync(deg, 0, (long)N * sizeof(int));
    gemm1_hist_kernel<<<gblocks + hblocks, 256>>>(x, W1, t, N, gblocks,
                                                  row, deg, E);
    scan_kernel<<<1, 1024>>>(deg, starts, cursor, stats, N);
    permute_kernel<<<eblocks, 256>>>(row, col, ew, cursor, epack, E);

    // ---------------- Layer 1 (aggregate + stats) ----------------
    gather96_kernel<<<nwarp_blocks, 256>>>(starts, epack, t, agg, N);
    stats96_kernel<<<256, 192>>>(agg, stats1, N);

    // ---------------- Layer 2 ----------------
    gemm_bn_kernel<96,96><<<gblocks, 256>>>(agg, W2, stats1, g1, be1, t, N);
    gather96_kernel<<<nwarp_blocks, 256>>>(starts, epack, t, agg, N);
    stats96_kernel<<<256, 192>>>(agg, stats2, N);

    // ---------------- Layer 3 ----------------
    gemm_bn_kernel<96,64><<<gblocks, 256>>>(agg, W3, stats2, g2, be2, t, N);
    gather64_lsm_kernel<<<nwarp_blocks, 256>>>(starts, epack, t, b3, out, N);
}